// round 15
// baseline (speedup 1.0000x reference)
#include <cuda_runtime.h>
#include <cuda_fp16.h>
#include <math.h>
#include <stdint.h>

#define BB 2
#define SS 2048
#define HH 16
#define NOPE 128
#define ROPE 64
#define VD 128
#define DQK 192           // NOPE + ROPE
#define QR 1536
#define KVR 512
#define NQ (HH*DQK)       // 3072
#define NKV (HH*(NOPE+VD))// 4096
#define MM (BB*SS)        // 4096
#define SCALE 0.07216878364870323f  // 1/sqrt(192)

// pure fp16 storage
__device__ __align__(256) unsigned short g_qh[(size_t)BB*HH*SS*DQK];   // [b,h,s,192]
__device__ __align__(256) unsigned short g_kh[(size_t)BB*HH*SS*DQK];   // [b,h,s,192]
__device__ __align__(256) unsigned short g_vth[(size_t)BB*HH*VD*SS];   // [b,h,d,s]
__device__ __align__(256) unsigned short g_qs_h[(size_t)MM*QR];
__device__ __align__(256) unsigned short g_kvs_h[(size_t)MM*KVR];
__device__ __align__(256) unsigned short g_wuq_h[(size_t)NQ*QR];
__device__ __align__(256) unsigned short g_wukv_h[(size_t)NKV*KVR];

// ---------------------------------------------------------------------------
// helpers
// ---------------------------------------------------------------------------
__device__ __forceinline__ uint32_t smem_u32(const void* p) {
    uint32_t a;
    asm("{ .reg .u64 t; cvta.to.shared.u64 t, %1; cvt.u32.u64 %0, t; }" : "=r"(a) : "l"(p));
    return a;
}
__device__ __forceinline__ void ldsm4(uint32_t* r, uint32_t addr) {
    asm volatile("ldmatrix.sync.aligned.m8n8.x4.shared.b16 {%0,%1,%2,%3}, [%4];"
                 : "=r"(r[0]), "=r"(r[1]), "=r"(r[2]), "=r"(r[3]) : "r"(addr));
}
__device__ __forceinline__ void mma16(float* c, const uint32_t* a, const uint32_t* b) {
    asm volatile("mma.sync.aligned.m16n8k16.row.col.f32.f16.f16.f32 "
                 "{%0,%1,%2,%3}, {%4,%5,%6,%7}, {%8,%9}, {%0,%1,%2,%3};"
                 : "+f"(c[0]), "+f"(c[1]), "+f"(c[2]), "+f"(c[3])
                 : "r"(a[0]), "r"(a[1]), "r"(a[2]), "r"(a[3]), "r"(b[0]), "r"(b[1]));
}
__device__ __forceinline__ void cpasync16(uint32_t sdst, const void* gsrc) {
    asm volatile("cp.async.cg.shared.global [%0], [%1], 16;" :: "r"(sdst), "l"(gsrc));
}
#define CP_COMMIT() asm volatile("cp.async.commit_group;" ::: "memory")
#define CP_WAIT(N)  asm volatile("cp.async.wait_group %0;" :: "n"(N) : "memory")

__device__ __forceinline__ uint32_t pack2(float x, float y) {
    __half2 h = __floats2half2_rn(x, y);
    return *(uint32_t*)&h;
}

// ---------------------------------------------------------------------------
// fused presplit: float -> fp16 for all four operand arrays in one launch
// ---------------------------------------------------------------------------
#define N4_Q   (MM*QR/4)
#define N4_KV  (MM*KVR/4)
#define N4_WQ  (NQ*QR/4)
#define N4_WKV (NKV*KVR/4)
#define N4_TOT (N4_Q + N4_KV + N4_WQ + N4_WKV)

__global__ void presplit_all_kernel(const float* __restrict__ Q,
                                    const float* __restrict__ KV,
                                    const float* __restrict__ WUQ,
                                    const float* __restrict__ WUKV) {
    int i = blockIdx.x * blockDim.x + threadIdx.x;
    if (i >= N4_TOT) return;
    const float* src;
    unsigned short* dst;
    int j = i;
    if (j < N4_Q)                { src = Q;    dst = g_qs_h; }
    else if ((j -= N4_Q)  < N4_KV) { src = KV;   dst = g_kvs_h; }
    else if ((j -= N4_KV) < N4_WQ) { src = WUQ;  dst = g_wuq_h; }
    else { j -= N4_WQ;             src = WUKV; dst = g_wukv_h; }
    float4 v = ((const float4*)src)[j];
    ushort4 hh;
    hh.x = __half_as_ushort(__float2half_rn(v.x));
    hh.y = __half_as_ushort(__float2half_rn(v.y));
    hh.z = __half_as_ushort(__float2half_rn(v.z));
    hh.w = __half_as_ushort(__float2half_rn(v.w));
    ((ushort4*)dst)[j] = hh;
}

// ---------------------------------------------------------------------------
// GEMM (pure fp16): CTA 128x128, 512 thr (16 warps 4m x 4n), Kc=64,
// 3-stage cp.async pipeline, one barrier per chunk.
// ---------------------------------------------------------------------------
#define GP 72                 // smem row pitch (halfs) for Kc=64
#define GTILE (128*GP)
#define GSTAGE (2*GTILE*2)    // bytes per stage (Ah, Wh) = 36864
#define GSMEM_TOTAL (3*GSTAGE)

extern __shared__ char gsm[];

template<int MODE>
__global__ __launch_bounds__(512) void gemm_mma_kernel() {
    const unsigned short* Ah = (MODE == 0) ? g_qs_h : g_kvs_h;
    const unsigned short* Wh = (MODE == 0) ? g_wuq_h : g_wukv_h;
    const int K = (MODE == 0) ? QR : KVR;

    const int tid = threadIdx.x;
    const int w = tid >> 5, lane = tid & 31;
    const int g = lane >> 2, t = lane & 3;
    const int lrow = lane & 15, lc8 = (lane >> 4) << 3;
    const int bm = blockIdx.y * 128, bn = blockIdx.x * 128;
    const int mw = (w >> 2) * 32, nw = (w & 3) * 32;
    const uint32_t uS = smem_u32(gsm);

    int rr[2], rf[2];
#pragma unroll
    for (int i = 0; i < 2; i++) {
        int idx = tid + i * 512;
        rr[i] = idx >> 3; rf[i] = (idx & 7) << 3;
    }

    auto issue_stage = [&](int s, int k0) {
        const uint32_t base = uS + s * GSTAGE;
#pragma unroll
        for (int i = 0; i < 2; i++) {
            const uint32_t off = (uint32_t)((rr[i] * GP + rf[i]) * 2);
            cpasync16(base + off,             Ah + (size_t)(bm + rr[i]) * K + k0 + rf[i]);
            cpasync16(base + GTILE * 2 + off, Wh + (size_t)(bn + rr[i]) * K + k0 + rf[i]);
        }
    };

    float c[2][4][4] = {};
    const int nc = K >> 6;   // chunks of 64 (>= 8 always)
    issue_stage(0, 0);
    CP_COMMIT();
    issue_stage(1, 64);
    CP_COMMIT();

    for (int cc = 0; cc < nc; cc++) {
        const int s = cc % 3;
        if (cc + 1 < nc) { CP_WAIT(1); } else { CP_WAIT(0); }
        __syncthreads();
        if (cc + 2 < nc) {
            issue_stage((cc + 2) % 3, (cc + 2) << 6);
            CP_COMMIT();
        }

        const uint32_t uAh = uS + s * GSTAGE;
        const uint32_t uWh = uAh + GTILE * 2;
#pragma unroll
        for (int kk = 0; kk < 4; kk++) {
            const int kb = kk << 4;
            uint32_t ah[2][4];
#pragma unroll
            for (int mf = 0; mf < 2; mf++) {
                uint32_t off = (uint32_t)(((mw + mf * 16 + lrow) * GP + kb + lc8) * 2);
                ldsm4(ah[mf], uAh + off);
            }
#pragma unroll
            for (int p = 0; p < 2; p++) {
                uint32_t off = (uint32_t)(((nw + p * 16 + lrow) * GP + kb + lc8) * 2);
                uint32_t b4h[4];
                ldsm4(b4h, uWh + off);
                uint32_t bhe[2] = {b4h[0], b4h[2]}, bho[2] = {b4h[1], b4h[3]};
#pragma unroll
                for (int mf = 0; mf < 2; mf++) {
                    mma16(c[mf][2 * p],     ah[mf], bhe);
                    mma16(c[mf][2 * p + 1], ah[mf], bho);
                }
            }
        }
    }

    // epilogue
#pragma unroll
    for (int mf = 0; mf < 2; mf++) {
#pragma unroll
        for (int i = 0; i < 4; i++) {
            const int m = bm + mw + mf * 16 + g + ((i >> 1) << 3);
            const int b = m >> 11, sidx = m & 2047;
#pragma unroll
            for (int nf = 0; nf < 4; nf++) {
                const int n = bn + nw + nf * 8 + (t << 1) + (i & 1);
                const unsigned short hv = __half_as_ushort(__float2half_rn(c[mf][nf][i]));
                if (MODE == 0) {
                    const int h = n / DQK, d = n % DQK;
                    g_qh[(((size_t)(b * HH + h)) * SS + sidx) * DQK + d] = hv;
                } else {
                    const int h = n >> 8, d = n & 255;
                    if (d < NOPE)
                        g_kh[(((size_t)(b * HH + h)) * SS + sidx) * DQK + d] = hv;
                    else
                        g_vth[(((size_t)(b * HH + h)) * VD + (d - NOPE)) * SS + sidx] = hv;
                }
            }
        }
    }
}

// ---------------------------------------------------------------------------
// RoPE (fp16 in/out)
// ---------------------------------------------------------------------------
__global__ void rope_kernel(const float* __restrict__ PE,
                            const float* __restrict__ cosb,
                            const float* __restrict__ sinb) {
    int tt = blockIdx.x * blockDim.x + threadIdx.x;
    if (tt >= BB * SS * 32) return;
    int i = tt & 31;
    int bs = tt >> 5;
    int b = bs / SS, s = bs % SS;

    float c  = cosb[(size_t)bs * ROPE + i];
    float sn = sinb[(size_t)bs * ROPE + i];

    float p1 = PE[(size_t)bs * ROPE + i];
    float p2 = PE[(size_t)bs * ROPE + i + 32];
    unsigned short k1 = __half_as_ushort(__float2half_rn(p1 * c - p2 * sn));
    unsigned short k2 = __half_as_ushort(__float2half_rn(p2 * c + p1 * sn));

#pragma unroll
    for (int h = 0; h < HH; h++) {
        size_t base = (((size_t)(b * HH + h)) * SS + s) * DQK + NOPE;
        float x1 = __half2float(__ushort_as_half(g_qh[base + i]));
        float x2 = __half2float(__ushort_as_half(g_qh[base + i + 32]));
        g_qh[base + i]      = __half_as_ushort(__float2half_rn(x1 * c - x2 * sn));
        g_qh[base + i + 32] = __half_as_ushort(__float2half_rn(x2 * c + x1 * sn));
        g_kh[base + i]      = k1;
        g_kh[base + i + 32] = k2;
    }
}

// ---------------------------------------------------------------------------
// Flash attention (causal): BQ=128, BK=64, 256 threads (8 warps x m16).
// Pure fp16; 3-stage K/V cp.async ring (1 barrier/iter); Q frags hoisted.
// ---------------------------------------------------------------------------
#define QP2 200   // Q/K smem pitch (halfs)
#define VP2 72    // V pitch (halfs)
#define FK_OFF  (128*QP2)                  // after sQh
#define FV_OFF  (FK_OFF + 3*64*QP2)
#define FL_SMEM_BYTES ((FV_OFF + 3*128*VP2) * 2)   // 183296 B

extern __shared__ unsigned short fsm2[];

__global__ __launch_bounds__(256, 1) void flash_kernel(float* __restrict__ out) {
    const int qt = gridDim.x - 1 - blockIdx.x;   // heavy CTAs first
    const int h = blockIdx.y, b = blockIdx.z;
    const int tid = threadIdx.x;
    const int w = tid >> 5, lane = tid & 31;
    const int g = lane >> 2, t = lane & 3;
    const int lrow = lane & 15, lc8 = (lane >> 4) << 3;

    const uint32_t uS  = smem_u32(fsm2);
    const uint32_t uQh = uS;

    const int wm = w * 16;
    const int q0 = qt * 128;
    const size_t bh = (size_t)(b * HH + h);
    const size_t qgbase = (bh * SS + q0) * DQK;
    const size_t kgbase = bh * SS * DQK;
    const size_t vgbase = bh * VD * SS;

    const int krow[6] = {(tid + 0) / 24, (tid + 256) / 24, (tid + 512) / 24,
                         (tid + 768) / 24, (tid + 1024) / 24, (tid + 1280) / 24};
    const int kseg[6] = {(tid + 0) % 24, (tid + 256) % 24, (tid + 512) % 24,
                         (tid + 768) % 24, (tid + 1024) % 24, (tid + 1280) % 24};
    const int vrow[4] = {(tid + 0) >> 3, (tid + 256) >> 3, (tid + 512) >> 3, (tid + 768) >> 3};
    const int vseg[4] = {(tid + 0) & 7, (tid + 256) & 7, (tid + 512) & 7, (tid + 768) & 7};

    auto issue_kv = [&](int s, int k0) {
        const uint32_t kb = uS + (FK_OFF + s * 64 * QP2) * 2;
        const uint32_t vb = uS + (FV_OFF + s * 128 * VP2) * 2;
#pragma unroll
        for (int i = 0; i < 6; i++)
            cpasync16(kb + (uint32_t)((krow[i] * QP2 + kseg[i] * 8) * 2),
                      g_kh + kgbase + (size_t)(k0 + krow[i]) * DQK + kseg[i] * 8);
#pragma unroll
        for (int i = 0; i < 4; i++)
            cpasync16(vb + (uint32_t)((vrow[i] * VP2 + vseg[i] * 8) * 2),
                      g_vth + vgbase + (size_t)vrow[i] * SS + k0 + vseg[i] * 8);
    };

    const int nkt = 2 * (qt + 1);

    // prologue: group 1 = Q tile + stage-0 K/V ; group 2 = stage-1 K/V
#pragma unroll
    for (int i = 0; i < 12; i++) {
        int idx = tid + i * 256;
        int r = idx / 24, sg = idx % 24;
        cpasync16(uS + (uint32_t)((r * QP2 + sg * 8) * 2),
                  g_qh + qgbase + (size_t)r * DQK + sg * 8);
    }
    issue_kv(0, 0);
    CP_COMMIT();
    if (nkt > 1) {
        issue_kv(1, 64);
        CP_COMMIT();
    }

    const int r0g = q0 + wm + g;
    const int r1g = r0g + 8;

    uint32_t qf[12][4];        // hoisted Q A-fragments (full k=192)
    float po[16][4] = {};
    float m0 = -1e30f, m1 = -1e30f, l0 = 0.f, l1 = 0.f;

    for (int kt = 0; kt < nkt; kt++) {
        const int k0 = kt * 64;
        const int s = kt % 3;
        if (kt + 1 < nkt) { CP_WAIT(1); } else { CP_WAIT(0); }
        __syncthreads();
        if (kt + 2 < nkt) {
            issue_kv((kt + 2) % 3, k0 + 128);
            CP_COMMIT();
        }
        if (kt == 0) {
#pragma unroll
            for (int kk = 0; kk < 12; kk++)
                ldsm4(qf[kk], uQh + (uint32_t)(((wm + lrow) * QP2 + (kk << 4) + lc8) * 2));
        }

        if (k0 <= q0 + wm + 15) {
            const uint32_t uKh = uS + (FK_OFF + s * 64 * QP2) * 2;
            const uint32_t uVh = uS + (FV_OFF + s * 128 * VP2) * 2;

            // ---- scores ----
            float sc[8][4] = {};
#pragma unroll
            for (int kk = 0; kk < 12; kk++) {
                const int kb = kk << 4;
#pragma unroll
                for (int p = 0; p < 4; p++) {
                    uint32_t b4h[4];
                    ldsm4(b4h, uKh + (uint32_t)(((p * 16 + lrow) * QP2 + kb + lc8) * 2));
                    uint32_t bhe[2] = {b4h[0], b4h[2]}, bho[2] = {b4h[1], b4h[3]};
                    mma16(sc[2 * p],     qf[kk], bhe);
                    mma16(sc[2 * p + 1], qf[kk], bho);
                }
            }

            // ---- mask + scale + register online softmax ----
            const bool needmask = (k0 + 63 > r0g);
            float mx0 = -1e30f, mx1 = -1e30f;
#pragma unroll
            for (int nf = 0; nf < 8; nf++) {
                const int c0 = k0 + nf * 8 + (t << 1);
                if (needmask) {
                    sc[nf][0] = (c0     > r0g) ? -1e30f : sc[nf][0] * SCALE;
                    sc[nf][1] = (c0 + 1 > r0g) ? -1e30f : sc[nf][1] * SCALE;
                    sc[nf][2] = (c0     > r1g) ? -1e30f : sc[nf][2] * SCALE;
                    sc[nf][3] = (c0 + 1 > r1g) ? -1e30f : sc[nf][3] * SCALE;
                } else {
                    sc[nf][0] *= SCALE; sc[nf][1] *= SCALE;
                    sc[nf][2] *= SCALE; sc[nf][3] *= SCALE;
                }
                mx0 = fmaxf(mx0, fmaxf(sc[nf][0], sc[nf][1]));
                mx1 = fmaxf(mx1, fmaxf(sc[nf][2], sc[nf][3]));
            }
            mx0 = fmaxf(mx0, __shfl_xor_sync(0xffffffffu, mx0, 1));
            mx0 = fmaxf(mx0, __shfl_xor_sync(0xffffffffu, mx0, 2));
            mx1 = fmaxf(mx1, __shfl_xor_sync(0xffffffffu, mx1, 1));
            mx1 = fmaxf(mx1, __shfl_xor_sync(0xffffffffu, mx1, 2));
            mx0 = fmaxf(mx0, m0);
            mx1 = fmaxf(mx1, m1);
            const float al0 = __expf(m0 - mx0);
            const float al1 = __expf(m1 - mx1);
            m0 = mx0; m1 = mx1;

            uint32_t pah[4][4];
            float s0 = 0.f, s1 = 0.f;
#pragma unroll
            for (int j = 0; j < 4; j++) {
                float p00 = __expf(sc[2 * j][0] - mx0), p01 = __expf(sc[2 * j][1] - mx0);
                float p10 = __expf(sc[2 * j][2] - mx1), p11 = __expf(sc[2 * j][3] - mx1);
                float q00 = __expf(sc[2 * j + 1][0] - mx0), q01 = __expf(sc[2 * j + 1][1] - mx0);
                float q10 = __expf(sc[2 * j + 1][2] - mx1), q11 = __expf(sc[2 * j + 1][3] - mx1);
                s0 += p00 + p01 + q00 + q01;
                s1 += p10 + p11 + q10 + q11;
                pah[j][0] = pack2(p00, p01);
                pah[j][1] = pack2(p10, p11);
                pah[j][2] = pack2(q00, q01);
                pah[j][3] = pack2(q10, q11);
            }
            s0 += __shfl_xor_sync(0xffffffffu, s0, 1);
            s0 += __shfl_xor_sync(0xffffffffu, s0, 2);
            s1 += __shfl_xor_sync(0xffffffffu, s1, 1);
            s1 += __shfl_xor_sync(0xffffffffu, s1, 2);
            l0 = l0 * al0 + s0;
            l1 = l1 * al1 + s1;

            // ---- PV ----
#pragma unroll
            for (int nf = 0; nf < 16; nf++) {
                po[nf][0] *= al0; po[nf][1] *= al0;
                po[nf][2] *= al1; po[nf][3] *= al1;
            }
#pragma unroll
            for (int j = 0; j < 4; j++) {
                const int kb = j << 4;
#pragma unroll
                for (int p = 0; p < 8; p++) {
                    uint32_t b4h[4];
                    ldsm4(b4h, uVh + (uint32_t)(((p * 16 + lrow) * VP2 + kb + lc8) * 2));
                    uint32_t bhe[2] = {b4h[0], b4h[2]}, bho[2] = {b4h[1], b4h[3]};
                    mma16(po[2 * p],     pah[j], bhe);
                    mma16(po[2 * p + 1], pah[j], bho);
                }
            }
        }
    }

    // epilogue
    {
        const float iv0 = 1.f / l0;
        const float iv1 = 1.f / l1;
        const size_t ob0 = (((size_t)b * SS + r0g) * HH + h) * VD;
        const size_t ob1 = (((size_t)b * SS + r1g) * HH + h) * VD;
#pragma unroll
        for (int nf = 0; nf < 16; nf++) {
            const int cl = nf * 8 + (t << 1);
            *(float2*)&out[ob0 + cl] = make_float2(po[nf][0] * iv0, po[nf][1] * iv0);
            *(float2*)&out[ob1 + cl] = make_float2(po[nf][2] * iv1, po[nf][3] * iv1);
        }
    }
}

// ---------------------------------------------------------------------------
extern "C" void kernel_launch(void* const* d_in, const int* in_sizes, int n_in,
                              void* d_out, int out_size) {
    const float* Q    = (const float*)d_in[0];
    const float* KV   = (const float*)d_in[1];
    const float* PE   = (const float*)d_in[2];
    const float* WUQ  = (const float*)d_in[3];
    const float* WUKV = (const float*)d_in[4];
    const float* cosb = (const float*)d_in[5];
    const float* sinb = (const float*)d_in[6];
    float* out = (float*)d_out;
    (void)in_sizes; (void)n_in; (void)out_size;

    cudaFuncSetAttribute(flash_kernel, cudaFuncAttributeMaxDynamicSharedMemorySize,
                         FL_SMEM_BYTES);
    cudaFuncSetAttribute(gemm_mma_kernel<0>, cudaFuncAttributeMaxDynamicSharedMemorySize,
                         GSMEM_TOTAL);
    cudaFuncSetAttribute(gemm_mma_kernel<1>, cudaFuncAttributeMaxDynamicSharedMemorySize,
                         GSMEM_TOTAL);

    presplit_all_kernel<<<(N4_TOT + 255) / 256, 256>>>(Q, KV, WUQ, WUKV);

    dim3 g1(NQ / 128, MM / 128);   // (24, 32)
    gemm_mma_kernel<0><<<g1, 512, GSMEM_TOTAL>>>();

    dim3 g2(NKV / 128, MM / 128);  // (32, 32)
    gemm_mma_kernel<1><<<g2, 512, GSMEM_TOTAL>>>();

    int nrope = BB * SS * 32;
    rope_kernel<<<(nrope + 255) / 256, 256>>>(PE, cosb, sinb);

    dim3 gf(SS / 128, HH, BB);     // (32, 16, 2)
    flash_kernel<<<gf, 256, FL_SMEM_BYTES>>>(out);
}

// round 16
// speedup vs baseline: 1.0578x; 1.0578x over previous
#include <cuda_runtime.h>
#include <cuda_fp16.h>
#include <math.h>
#include <stdint.h>

#define BB 2
#define SS 2048
#define HH 16
#define NOPE 128
#define ROPE 64
#define VD 128
#define DQK 192           // NOPE + ROPE
#define QR 1536
#define KVR 512
#define NQ (HH*DQK)       // 3072
#define NKV (HH*(NOPE+VD))// 4096
#define MM (BB*SS)        // 4096
#define SCALE 0.07216878364870323f  // 1/sqrt(192)

// pure fp16 storage
__device__ __align__(256) unsigned short g_qh[(size_t)BB*HH*SS*DQK];   // [b,h,s,192]
__device__ __align__(256) unsigned short g_kh[(size_t)BB*HH*SS*DQK];   // [b,h,s,192]
__device__ __align__(256) unsigned short g_vth[(size_t)BB*HH*VD*SS];   // [b,h,d,s]
__device__ __align__(256) unsigned short g_qs_h[(size_t)MM*QR];
__device__ __align__(256) unsigned short g_kvs_h[(size_t)MM*KVR];
__device__ __align__(256) unsigned short g_wuq_h[(size_t)NQ*QR];
__device__ __align__(256) unsigned short g_wukv_h[(size_t)NKV*KVR];

// ---------------------------------------------------------------------------
// helpers
// ---------------------------------------------------------------------------
__device__ __forceinline__ uint32_t smem_u32(const void* p) {
    uint32_t a;
    asm("{ .reg .u64 t; cvta.to.shared.u64 t, %1; cvt.u32.u64 %0, t; }" : "=r"(a) : "l"(p));
    return a;
}
__device__ __forceinline__ void ldsm4(uint32_t* r, uint32_t addr) {
    asm volatile("ldmatrix.sync.aligned.m8n8.x4.shared.b16 {%0,%1,%2,%3}, [%4];"
                 : "=r"(r[0]), "=r"(r[1]), "=r"(r[2]), "=r"(r[3]) : "r"(addr));
}
__device__ __forceinline__ void mma16(float* c, const uint32_t* a, const uint32_t* b) {
    asm volatile("mma.sync.aligned.m16n8k16.row.col.f32.f16.f16.f32 "
                 "{%0,%1,%2,%3}, {%4,%5,%6,%7}, {%8,%9}, {%0,%1,%2,%3};"
                 : "+f"(c[0]), "+f"(c[1]), "+f"(c[2]), "+f"(c[3])
                 : "r"(a[0]), "r"(a[1]), "r"(a[2]), "r"(a[3]), "r"(b[0]), "r"(b[1]));
}
__device__ __forceinline__ void cpasync16(uint32_t sdst, const void* gsrc) {
    asm volatile("cp.async.cg.shared.global [%0], [%1], 16;" :: "r"(sdst), "l"(gsrc));
}
#define CP_COMMIT() asm volatile("cp.async.commit_group;" ::: "memory")
#define CP_WAIT(N)  asm volatile("cp.async.wait_group %0;" :: "n"(N) : "memory")

__device__ __forceinline__ uint32_t pack2(float x, float y) {
    __half2 h = __floats2half2_rn(x, y);
    return *(uint32_t*)&h;
}

// ---------------------------------------------------------------------------
// fused presplit
// ---------------------------------------------------------------------------
#define N4_Q   (MM*QR/4)
#define N4_KV  (MM*KVR/4)
#define N4_WQ  (NQ*QR/4)
#define N4_WKV (NKV*KVR/4)
#define N4_TOT (N4_Q + N4_KV + N4_WQ + N4_WKV)

__global__ void presplit_all_kernel(const float* __restrict__ Q,
                                    const float* __restrict__ KV,
                                    const float* __restrict__ WUQ,
                                    const float* __restrict__ WUKV) {
    int i = blockIdx.x * blockDim.x + threadIdx.x;
    if (i >= N4_TOT) return;
    const float* src;
    unsigned short* dst;
    int j = i;
    if (j < N4_Q)                  { src = Q;    dst = g_qs_h; }
    else if ((j -= N4_Q)  < N4_KV) { src = KV;   dst = g_kvs_h; }
    else if ((j -= N4_KV) < N4_WQ) { src = WUQ;  dst = g_wuq_h; }
    else { j -= N4_WQ;               src = WUKV; dst = g_wukv_h; }
    float4 v = ((const float4*)src)[j];
    ushort4 hh;
    hh.x = __half_as_ushort(__float2half_rn(v.x));
    hh.y = __half_as_ushort(__float2half_rn(v.y));
    hh.z = __half_as_ushort(__float2half_rn(v.z));
    hh.w = __half_as_ushort(__float2half_rn(v.w));
    ((ushort4*)dst)[j] = hh;
}

// ---------------------------------------------------------------------------
// Merged GEMM (pure fp16): one launch for both projections.
// CTA 128x128, 512 thr (16 warps 4m x 4n), Kc=64, 3-stage cp.async.
// blocks [0, 768): MODE 0 (Q proj);  [768, 1792): MODE 1 (KV proj)
// ---------------------------------------------------------------------------
#define GP 72
#define GTILE (128*GP)
#define GSTAGE (2*GTILE*2)
#define GSMEM_TOTAL (3*GSTAGE)
#define G1_BLOCKS (24*32)
#define G_TOTAL (G1_BLOCKS + 32*32)

extern __shared__ char gsm[];

__global__ __launch_bounds__(512) void gemm_all_kernel() {
    const int bid = blockIdx.x;
    int mode, bm, bn, K;
    const unsigned short *Ah, *Wh;
    if (bid < G1_BLOCKS) {
        mode = 0; bn = (bid % 24) * 128; bm = (bid / 24) * 128;
        Ah = g_qs_h; Wh = g_wuq_h; K = QR;
    } else {
        const int b2 = bid - G1_BLOCKS;
        mode = 1; bn = (b2 & 31) * 128; bm = (b2 >> 5) * 128;
        Ah = g_kvs_h; Wh = g_wukv_h; K = KVR;
    }

    const int tid = threadIdx.x;
    const int w = tid >> 5, lane = tid & 31;
    const int g = lane >> 2, t = lane & 3;
    const int lrow = lane & 15, lc8 = (lane >> 4) << 3;
    const int mw = (w >> 2) * 32, nw = (w & 3) * 32;
    const uint32_t uS = smem_u32(gsm);

    int rr[2], rf[2];
#pragma unroll
    for (int i = 0; i < 2; i++) {
        int idx = tid + i * 512;
        rr[i] = idx >> 3; rf[i] = (idx & 7) << 3;
    }

    auto issue_stage = [&](int s, int k0) {
        const uint32_t base = uS + s * GSTAGE;
#pragma unroll
        for (int i = 0; i < 2; i++) {
            const uint32_t off = (uint32_t)((rr[i] * GP + rf[i]) * 2);
            cpasync16(base + off,             Ah + (size_t)(bm + rr[i]) * K + k0 + rf[i]);
            cpasync16(base + GTILE * 2 + off, Wh + (size_t)(bn + rr[i]) * K + k0 + rf[i]);
        }
    };

    float c[2][4][4] = {};
    const int nc = K >> 6;
    issue_stage(0, 0);
    CP_COMMIT();
    issue_stage(1, 64);
    CP_COMMIT();

    for (int cc = 0; cc < nc; cc++) {
        const int s = cc % 3;
        if (cc + 1 < nc) { CP_WAIT(1); } else { CP_WAIT(0); }
        __syncthreads();
        if (cc + 2 < nc) {
            issue_stage((cc + 2) % 3, (cc + 2) << 6);
            CP_COMMIT();
        }

        const uint32_t uAh = uS + s * GSTAGE;
        const uint32_t uWh = uAh + GTILE * 2;
#pragma unroll
        for (int kk = 0; kk < 4; kk++) {
            const int kb = kk << 4;
            uint32_t ah[2][4];
#pragma unroll
            for (int mf = 0; mf < 2; mf++) {
                uint32_t off = (uint32_t)(((mw + mf * 16 + lrow) * GP + kb + lc8) * 2);
                ldsm4(ah[mf], uAh + off);
            }
#pragma unroll
            for (int p = 0; p < 2; p++) {
                uint32_t off = (uint32_t)(((nw + p * 16 + lrow) * GP + kb + lc8) * 2);
                uint32_t b4h[4];
                ldsm4(b4h, uWh + off);
                uint32_t bhe[2] = {b4h[0], b4h[2]}, bho[2] = {b4h[1], b4h[3]};
#pragma unroll
                for (int mf = 0; mf < 2; mf++) {
                    mma16(c[mf][2 * p],     ah[mf], bhe);
                    mma16(c[mf][2 * p + 1], ah[mf], bho);
                }
            }
        }
    }

    // epilogue: vectorize pair stores where destination is d-contiguous
#pragma unroll
    for (int mf = 0; mf < 2; mf++) {
#pragma unroll
        for (int ri = 0; ri < 2; ri++) {          // row = m, m+8
            const int m = bm + mw + mf * 16 + g + (ri << 3);
            const int b = m >> 11, sidx = m & 2047;
#pragma unroll
            for (int nf = 0; nf < 4; nf++) {
                const int n = bn + nw + nf * 8 + (t << 1);   // even; pair n, n+1
                const float v0 = c[mf][nf][ri * 2 + 0];
                const float v1 = c[mf][nf][ri * 2 + 1];
                if (mode == 0) {
                    const int h = n / DQK, d = n % DQK;
                    *(uint32_t*)&g_qh[(((size_t)(b * HH + h)) * SS + sidx) * DQK + d] = pack2(v0, v1);
                } else {
                    const int h = n >> 8, d = n & 255;
                    if (d < NOPE) {
                        *(uint32_t*)&g_kh[(((size_t)(b * HH + h)) * SS + sidx) * DQK + d] = pack2(v0, v1);
                    } else {
                        const size_t vb = ((size_t)(b * HH + h)) * VD + (d - NOPE);
                        g_vth[vb * SS + sidx]       = __half_as_ushort(__float2half_rn(v0));
                        g_vth[(vb + 1) * SS + sidx] = __half_as_ushort(__float2half_rn(v1));
                    }
                }
            }
        }
    }
}

// ---------------------------------------------------------------------------
// RoPE, vectorized: one thread per (b, s, h)
// ---------------------------------------------------------------------------
__global__ void rope_kernel(const float* __restrict__ PE,
                            const float* __restrict__ cosb,
                            const float* __restrict__ sinb) {
    int tt = blockIdx.x * blockDim.x + threadIdx.x;
    if (tt >= BB * SS * HH) return;
    const int h = tt & 15;
    const int bs = tt >> 4;
    const int b = bs >> 11, s = bs & 2047;
    const size_t base = (((size_t)(b * HH + h)) * SS + s) * DQK + NOPE;
    const size_t pb = (size_t)bs * ROPE;

#pragma unroll
    for (int cch = 0; cch < 4; cch++) {
        const int i0 = cch * 8;
        uint4 vlo = *(const uint4*)(g_qh + base + i0);
        uint4 vhi = *(const uint4*)(g_qh + base + 32 + i0);
        float4 ca = *(const float4*)(cosb + pb + i0);
        float4 cb = *(const float4*)(cosb + pb + i0 + 4);
        float4 sa = *(const float4*)(sinb + pb + i0);
        float4 sb = *(const float4*)(sinb + pb + i0 + 4);
        float4 pa = *(const float4*)(PE + pb + i0);
        float4 pb4 = *(const float4*)(PE + pb + i0 + 4);
        float4 qa = *(const float4*)(PE + pb + 32 + i0);
        float4 qb = *(const float4*)(PE + pb + 32 + i0 + 4);

        const float cc[8] = {ca.x, ca.y, ca.z, ca.w, cb.x, cb.y, cb.z, cb.w};
        const float ss[8] = {sa.x, sa.y, sa.z, sa.w, sb.x, sb.y, sb.z, sb.w};
        const float p1[8] = {pa.x, pa.y, pa.z, pa.w, pb4.x, pb4.y, pb4.z, pb4.w};
        const float p2[8] = {qa.x, qa.y, qa.z, qa.w, qb.x, qb.y, qb.z, qb.w};
        const uint32_t wl[4] = {vlo.x, vlo.y, vlo.z, vlo.w};
        const uint32_t wh[4] = {vhi.x, vhi.y, vhi.z, vhi.w};

        uint32_t ol[4], oh[4], kl[4], kh[4];
#pragma unroll
        for (int k = 0; k < 4; k++) {
            float2 x1 = __half22float2(*(const __half2*)&wl[k]);
            float2 x2 = __half22float2(*(const __half2*)&wh[k]);
            const int e0 = 2 * k, e1 = 2 * k + 1;
            ol[k] = pack2(x1.x * cc[e0] - x2.x * ss[e0], x1.y * cc[e1] - x2.y * ss[e1]);
            oh[k] = pack2(x2.x * cc[e0] + x1.x * ss[e0], x2.y * cc[e1] + x1.y * ss[e1]);
            kl[k] = pack2(p1[e0] * cc[e0] - p2[e0] * ss[e0], p1[e1] * cc[e1] - p2[e1] * ss[e1]);
            kh[k] = pack2(p2[e0] * cc[e0] + p1[e0] * ss[e0], p2[e1] * cc[e1] + p1[e1] * ss[e1]);
        }
        *(uint4*)(g_qh + base + i0)      = make_uint4(ol[0], ol[1], ol[2], ol[3]);
        *(uint4*)(g_qh + base + 32 + i0) = make_uint4(oh[0], oh[1], oh[2], oh[3]);
        *(uint4*)(g_kh + base + i0)      = make_uint4(kl[0], kl[1], kl[2], kl[3]);
        *(uint4*)(g_kh + base + 32 + i0) = make_uint4(kh[0], kh[1], kh[2], kh[3]);
    }
}

// ---------------------------------------------------------------------------
// Flash attention (causal): BQ=128, BK=128, 256 threads (8 warps x m16).
// Pure fp16; 2-stage K/V cp.async; register softmax once per 128 cols.
// ---------------------------------------------------------------------------
#define QP2 200   // Q/K pitch (halfs)
#define VP3 136   // V pitch for 128 cols (halfs)
#define FK_OFF  (128*QP2)
#define FV_OFF  (FK_OFF + 2*128*QP2)
#define FL_SMEM_BYTES ((FV_OFF + 2*128*VP3) * 2)   // 223232 B

extern __shared__ unsigned short fsm2[];

__global__ __launch_bounds__(256, 1) void flash_kernel(float* __restrict__ out) {
    const int qt = gridDim.x - 1 - blockIdx.x;   // heavy CTAs first
    const int h = blockIdx.y, b = blockIdx.z;
    const int tid = threadIdx.x;
    const int w = tid >> 5, lane = tid & 31;
    const int g = lane >> 2, t = lane & 3;
    const int lrow = lane & 15, lc8 = (lane >> 4) << 3;

    const uint32_t uS  = smem_u32(fsm2);
    const uint32_t uQh = uS;

    const int wm = w * 16;
    const int q0 = qt * 128;
    const size_t bh = (size_t)(b * HH + h);
    const size_t qgbase = (bh * SS + q0) * DQK;
    const size_t kgbase = bh * SS * DQK;
    const size_t vgbase = bh * VD * SS;

    auto issue_kv = [&](int st, int k0) {
        const uint32_t kb = uS + (FK_OFF + st * 128 * QP2) * 2;
        const uint32_t vb = uS + (FV_OFF + st * 128 * VP3) * 2;
#pragma unroll
        for (int i = 0; i < 12; i++) {
            int idx = tid + i * 256;
            int r = idx / 24, sg = idx % 24;
            cpasync16(kb + (uint32_t)((r * QP2 + sg * 8) * 2),
                      g_kh + kgbase + (size_t)(k0 + r) * DQK + sg * 8);
        }
#pragma unroll
        for (int i = 0; i < 8; i++) {
            int idx = tid + i * 256;
            int r = idx >> 4, sg = idx & 15;
            cpasync16(vb + (uint32_t)((r * VP3 + sg * 8) * 2),
                      g_vth + vgbase + (size_t)r * SS + k0 + sg * 8);
        }
    };

    // prologue: Q tile + stage-0 K/V in group 0
#pragma unroll
    for (int i = 0; i < 12; i++) {
        int idx = tid + i * 256;
        int r = idx / 24, sg = idx % 24;
        cpasync16(uS + (uint32_t)((r * QP2 + sg * 8) * 2),
                  g_qh + qgbase + (size_t)r * DQK + sg * 8);
    }
    issue_kv(0, 0);
    CP_COMMIT();

    const int r0g = q0 + wm + g;
    const int r1g = r0g + 8;

    float po[16][4] = {};
    float m0 = -1e30f, m1 = -1e30f, l0 = 0.f, l1 = 0.f;

    const int nkt = qt + 1;   // tiles of 128
    for (int kt = 0; kt < nkt; kt++) {
        const int k0 = kt << 7;
        const int s = kt & 1;
        if (kt + 1 < nkt) {
            issue_kv(s ^ 1, k0 + 128);
            CP_COMMIT();
            CP_WAIT(1);
        } else {
            CP_WAIT(0);
        }
        __syncthreads();

        const uint32_t uKh = uS + (FK_OFF + s * 128 * QP2) * 2;
        const uint32_t uVh = uS + (FV_OFF + s * 128 * VP3) * 2;
        const bool diag = (kt == nkt - 1);
        const int pmax = diag ? (w + 1) : 8;   // 16-col K slabs this warp needs

        // ---- scores (full k=192, up to 128 cols) ----
        float sc[16][4] = {};
#pragma unroll
        for (int kk = 0; kk < 12; kk++) {
            const int kb = kk << 4;
            uint32_t ah[4];
            ldsm4(ah, uQh + (uint32_t)(((wm + lrow) * QP2 + kb + lc8) * 2));
#pragma unroll
            for (int p = 0; p < 8; p++) {
                if (p < pmax) {
                    uint32_t b4h[4];
                    ldsm4(b4h, uKh + (uint32_t)(((p * 16 + lrow) * QP2 + kb + lc8) * 2));
                    uint32_t bhe[2] = {b4h[0], b4h[2]}, bho[2] = {b4h[1], b4h[3]};
                    mma16(sc[2 * p],     ah, bhe);
                    mma16(sc[2 * p + 1], ah, bho);
                }
            }
        }

        // ---- mask + scale + online softmax (once per 128 cols) ----
        float mx0 = -1e30f, mx1 = -1e30f;
#pragma unroll
        for (int nf = 0; nf < 16; nf++) {
            if (nf >= 2 * pmax) {
                sc[nf][0] = sc[nf][1] = sc[nf][2] = sc[nf][3] = -1e30f;
            } else if (diag) {
                const int c0 = k0 + nf * 8 + (t << 1);
                sc[nf][0] = (c0     > r0g) ? -1e30f : sc[nf][0] * SCALE;
                sc[nf][1] = (c0 + 1 > r0g) ? -1e30f : sc[nf][1] * SCALE;
                sc[nf][2] = (c0     > r1g) ? -1e30f : sc[nf][2] * SCALE;
                sc[nf][3] = (c0 + 1 > r1g) ? -1e30f : sc[nf][3] * SCALE;
            } else {
                sc[nf][0] *= SCALE; sc[nf][1] *= SCALE;
                sc[nf][2] *= SCALE; sc[nf][3] *= SCALE;
            }
            mx0 = fmaxf(mx0, fmaxf(sc[nf][0], sc[nf][1]));
            mx1 = fmaxf(mx1, fmaxf(sc[nf][2], sc[nf][3]));
        }
        mx0 = fmaxf(mx0, __shfl_xor_sync(0xffffffffu, mx0, 1));
        mx0 = fmaxf(mx0, __shfl_xor_sync(0xffffffffu, mx0, 2));
        mx1 = fmaxf(mx1, __shfl_xor_sync(0xffffffffu, mx1, 1));
        mx1 = fmaxf(mx1, __shfl_xor_sync(0xffffffffu, mx1, 2));
        mx0 = fmaxf(mx0, m0);
        mx1 = fmaxf(mx1, m1);
        const float al0 = __expf(m0 - mx0);
        const float al1 = __expf(m1 - mx1);
        m0 = mx0; m1 = mx1;

        uint32_t pah[8][4];
        float s0 = 0.f, s1 = 0.f;
#pragma unroll
        for (int j = 0; j < 8; j++) {
            float p00 = __expf(sc[2 * j][0] - mx0), p01 = __expf(sc[2 * j][1] - mx0);
            float p10 = __expf(sc[2 * j][2] - mx1), p11 = __expf(sc[2 * j][3] - mx1);
            float q00 = __expf(sc[2 * j + 1][0] - mx0), q01 = __expf(sc[2 * j + 1][1] - mx0);
            float q10 = __expf(sc[2 * j + 1][2] - mx1), q11 = __expf(sc[2 * j + 1][3] - mx1);
            s0 += p00 + p01 + q00 + q01;
            s1 += p10 + p11 + q10 + q11;
            pah[j][0] = pack2(p00, p01);
            pah[j][1] = pack2(p10, p11);
            pah[j][2] = pack2(q00, q01);
            pah[j][3] = pack2(q10, q11);
        }
        s0 += __shfl_xor_sync(0xffffffffu, s0, 1);
        s0 += __shfl_xor_sync(0xffffffffu, s0, 2);
        s1 += __shfl_xor_sync(0xffffffffu, s1, 1);
        s1 += __shfl_xor_sync(0xffffffffu, s1, 2);
        l0 = l0 * al0 + s0;
        l1 = l1 * al1 + s1;

        // ---- PV (up to 128 k-cols) ----
#pragma unroll
        for (int nf = 0; nf < 16; nf++) {
            po[nf][0] *= al0; po[nf][1] *= al0;
            po[nf][2] *= al1; po[nf][3] *= al1;
        }
#pragma unroll
        for (int j = 0; j < 8; j++) {
            if (j < pmax) {
                const int kb = j << 4;
#pragma unroll
                for (int p = 0; p < 8; p++) {
                    uint32_t b4h[4];
                    ldsm4(b4h, uVh + (uint32_t)(((p * 16 + lrow) * VP3 + kb + lc8) * 2));
                    uint32_t bhe[2] = {b4h[0], b4h[2]}, bho[2] = {b4h[1], b4h[3]};
                    mma16(po[2 * p],     pah[j], bhe);
                    mma16(po[2 * p + 1], pah[j], bho);
                }
            }
        }
        __syncthreads();
    }

    // epilogue
    {
        const float iv0 = 1.f / l0;
        const float iv1 = 1.f / l1;
        const size_t ob0 = (((size_t)b * SS + r0g) * HH + h) * VD;
        const size_t ob1 = (((size_t)b * SS + r1g) * HH + h) * VD;
#pragma unroll
        for (int nf = 0; nf < 16; nf++) {
            const int cl = nf * 8 + (t << 1);
            *(float2*)&out[ob0 + cl] = make_float2(po[nf][0] * iv0, po[nf][1] * iv0);
            *(float2*)&out[ob1 + cl] = make_float2(po[nf][2] * iv1, po[nf][3] * iv1);
        }
    }
}

// ---------------------------------------------------------------------------
extern "C" void kernel_launch(void* const* d_in, const int* in_sizes, int n_in,
                              void* d_out, int out_size) {
    const float* Q    = (const float*)d_in[0];
    const float* KV   = (const float*)d_in[1];
    const float* PE   = (const float*)d_in[2];
    const float* WUQ  = (const float*)d_in[3];
    const float* WUKV = (const float*)d_in[4];
    const float* cosb = (const float*)d_in[5];
    const float* sinb = (const float*)d_in[6];
    float* out = (float*)d_out;
    (void)in_sizes; (void)n_in; (void)out_size;

    cudaFuncSetAttribute(flash_kernel, cudaFuncAttributeMaxDynamicSharedMemorySize,
                         FL_SMEM_BYTES);
    cudaFuncSetAttribute(gemm_all_kernel, cudaFuncAttributeMaxDynamicSharedMemorySize,
                         GSMEM_TOTAL);

    presplit_all_kernel<<<(N4_TOT + 255) / 256, 256>>>(Q, KV, WUQ, WUKV);

    gemm_all_kernel<<<G_TOTAL, 512, GSMEM_TOTAL>>>();

    int nrope = BB * SS * HH;
    rope_kernel<<<(nrope + 255) / 256, 256>>>(PE, cosb, sinb);

    dim3 gf(SS / 128, HH, BB);     // (16, 16, 2)
    flash_kernel<<<gf, 256, FL_SMEM_BYTES>>>(out);
}

// round 17
// speedup vs baseline: 1.1203x; 1.0590x over previous
#include <cuda_runtime.h>
#include <cuda_fp16.h>
#include <math.h>
#include <stdint.h>

#define BB 2
#define SS 2048
#define HH 16
#define NOPE 128
#define ROPE 64
#define VD 128
#define DQK 192           // NOPE + ROPE
#define QR 1536
#define KVR 512
#define NQ (HH*DQK)       // 3072
#define NKV (HH*(NOPE+VD))// 4096
#define MM (BB*SS)        // 4096
#define SCALE 0.07216878364870323f
#define SCALE2 0.10412811903427108f  // SCALE * log2(e)

// pure fp16 storage
__device__ __align__(256) unsigned short g_qh[(size_t)BB*HH*SS*DQK];   // [b,h,s,192]
__device__ __align__(256) unsigned short g_kh[(size_t)BB*HH*SS*DQK];   // [b,h,s,192]
__device__ __align__(256) unsigned short g_vth[(size_t)BB*HH*VD*SS];   // [b,h,d,s]
__device__ __align__(256) unsigned short g_qs_h[(size_t)MM*QR];
__device__ __align__(256) unsigned short g_kvs_h[(size_t)MM*KVR];
__device__ __align__(256) unsigned short g_wuq_h[(size_t)NQ*QR];
__device__ __align__(256) unsigned short g_wukv_h[(size_t)NKV*KVR];

// ---------------------------------------------------------------------------
// helpers
// ---------------------------------------------------------------------------
__device__ __forceinline__ uint32_t smem_u32(const void* p) {
    uint32_t a;
    asm("{ .reg .u64 t; cvta.to.shared.u64 t, %1; cvt.u32.u64 %0, t; }" : "=r"(a) : "l"(p));
    return a;
}
__device__ __forceinline__ void ldsm4(uint32_t* r, uint32_t addr) {
    asm volatile("ldmatrix.sync.aligned.m8n8.x4.shared.b16 {%0,%1,%2,%3}, [%4];"
                 : "=r"(r[0]), "=r"(r[1]), "=r"(r[2]), "=r"(r[3]) : "r"(addr));
}
__device__ __forceinline__ void mma16(float* c, const uint32_t* a, const uint32_t* b) {
    asm volatile("mma.sync.aligned.m16n8k16.row.col.f32.f16.f16.f32 "
                 "{%0,%1,%2,%3}, {%4,%5,%6,%7}, {%8,%9}, {%0,%1,%2,%3};"
                 : "+f"(c[0]), "+f"(c[1]), "+f"(c[2]), "+f"(c[3])
                 : "r"(a[0]), "r"(a[1]), "r"(a[2]), "r"(a[3]), "r"(b[0]), "r"(b[1]));
}
__device__ __forceinline__ void cpasync16(uint32_t sdst, const void* gsrc) {
    asm volatile("cp.async.cg.shared.global [%0], [%1], 16;" :: "r"(sdst), "l"(gsrc));
}
#define CP_COMMIT() asm volatile("cp.async.commit_group;" ::: "memory")
#define CP_WAIT(N)  asm volatile("cp.async.wait_group %0;" :: "n"(N) : "memory")

__device__ __forceinline__ uint32_t pack2(float x, float y) {
    __half2 h = __floats2half2_rn(x, y);
    return *(uint32_t*)&h;
}

// ---------------------------------------------------------------------------
// fused presplit
// ---------------------------------------------------------------------------
#define N4_Q   (MM*QR/4)
#define N4_KV  (MM*KVR/4)
#define N4_WQ  (NQ*QR/4)
#define N4_WKV (NKV*KVR/4)
#define N4_TOT (N4_Q + N4_KV + N4_WQ + N4_WKV)

__global__ void presplit_all_kernel(const float* __restrict__ Q,
                                    const float* __restrict__ KV,
                                    const float* __restrict__ WUQ,
                                    const float* __restrict__ WUKV) {
    int i = blockIdx.x * blockDim.x + threadIdx.x;
    if (i >= N4_TOT) return;
    const float* src;
    unsigned short* dst;
    int j = i;
    if (j < N4_Q)                  { src = Q;    dst = g_qs_h; }
    else if ((j -= N4_Q)  < N4_KV) { src = KV;   dst = g_kvs_h; }
    else if ((j -= N4_KV) < N4_WQ) { src = WUQ;  dst = g_wuq_h; }
    else { j -= N4_WQ;               src = WUKV; dst = g_wukv_h; }
    float4 v = ((const float4*)src)[j];
    ushort4 hh;
    hh.x = __half_as_ushort(__float2half_rn(v.x));
    hh.y = __half_as_ushort(__float2half_rn(v.y));
    hh.z = __half_as_ushort(__float2half_rn(v.z));
    hh.w = __half_as_ushort(__float2half_rn(v.w));
    ((ushort4*)dst)[j] = hh;
}

// ---------------------------------------------------------------------------
// Merged GEMM (pure fp16): CTA 128x128, 512 thr, Kc=64, 3-stage cp.async.
// ---------------------------------------------------------------------------
#define GP 72
#define GTILE (128*GP)
#define GSTAGE (2*GTILE*2)
#define GSMEM_TOTAL (3*GSTAGE)
#define G1_BLOCKS (24*32)
#define G_TOTAL (G1_BLOCKS + 32*32)

extern __shared__ char gsm[];

__global__ __launch_bounds__(512) void gemm_all_kernel() {
    const int bid = blockIdx.x;
    int mode, bm, bn, K;
    const unsigned short *Ah, *Wh;
    if (bid < G1_BLOCKS) {
        mode = 0; bn = (bid % 24) * 128; bm = (bid / 24) * 128;
        Ah = g_qs_h; Wh = g_wuq_h; K = QR;
    } else {
        const int b2 = bid - G1_BLOCKS;
        mode = 1; bn = (b2 & 31) * 128; bm = (b2 >> 5) * 128;
        Ah = g_kvs_h; Wh = g_wukv_h; K = KVR;
    }

    const int tid = threadIdx.x;
    const int w = tid >> 5, lane = tid & 31;
    const int g = lane >> 2, t = lane & 3;
    const int lrow = lane & 15, lc8 = (lane >> 4) << 3;
    const int mw = (w >> 2) * 32, nw = (w & 3) * 32;
    const uint32_t uS = smem_u32(gsm);

    int rr[2], rf[2];
#pragma unroll
    for (int i = 0; i < 2; i++) {
        int idx = tid + i * 512;
        rr[i] = idx >> 3; rf[i] = (idx & 7) << 3;
    }

    auto issue_stage = [&](int s, int k0) {
        const uint32_t base = uS + s * GSTAGE;
#pragma unroll
        for (int i = 0; i < 2; i++) {
            const uint32_t off = (uint32_t)((rr[i] * GP + rf[i]) * 2);
            cpasync16(base + off,             Ah + (size_t)(bm + rr[i]) * K + k0 + rf[i]);
            cpasync16(base + GTILE * 2 + off, Wh + (size_t)(bn + rr[i]) * K + k0 + rf[i]);
        }
    };

    float c[2][4][4] = {};
    const int nc = K >> 6;
    issue_stage(0, 0);
    CP_COMMIT();
    issue_stage(1, 64);
    CP_COMMIT();

    for (int cc = 0; cc < nc; cc++) {
        const int s = cc % 3;
        if (cc + 1 < nc) { CP_WAIT(1); } else { CP_WAIT(0); }
        __syncthreads();
        if (cc + 2 < nc) {
            issue_stage((cc + 2) % 3, (cc + 2) << 6);
            CP_COMMIT();
        }

        const uint32_t uAh = uS + s * GSTAGE;
        const uint32_t uWh = uAh + GTILE * 2;
#pragma unroll
        for (int kk = 0; kk < 4; kk++) {
            const int kb = kk << 4;
            uint32_t ah[2][4];
#pragma unroll
            for (int mf = 0; mf < 2; mf++) {
                uint32_t off = (uint32_t)(((mw + mf * 16 + lrow) * GP + kb + lc8) * 2);
                ldsm4(ah[mf], uAh + off);
            }
#pragma unroll
            for (int p = 0; p < 2; p++) {
                uint32_t off = (uint32_t)(((nw + p * 16 + lrow) * GP + kb + lc8) * 2);
                uint32_t b4h[4];
                ldsm4(b4h, uWh + off);
                uint32_t bhe[2] = {b4h[0], b4h[2]}, bho[2] = {b4h[1], b4h[3]};
#pragma unroll
                for (int mf = 0; mf < 2; mf++) {
                    mma16(c[mf][2 * p],     ah[mf], bhe);
                    mma16(c[mf][2 * p + 1], ah[mf], bho);
                }
            }
        }
    }

    // epilogue
#pragma unroll
    for (int mf = 0; mf < 2; mf++) {
#pragma unroll
        for (int ri = 0; ri < 2; ri++) {
            const int m = bm + mw + mf * 16 + g + (ri << 3);
            const int b = m >> 11, sidx = m & 2047;
#pragma unroll
            for (int nf = 0; nf < 4; nf++) {
                const int n = bn + nw + nf * 8 + (t << 1);
                const float v0 = c[mf][nf][ri * 2 + 0];
                const float v1 = c[mf][nf][ri * 2 + 1];
                if (mode == 0) {
                    const int h = n / DQK, d = n % DQK;
                    *(uint32_t*)&g_qh[(((size_t)(b * HH + h)) * SS + sidx) * DQK + d] = pack2(v0, v1);
                } else {
                    const int h = n >> 8, d = n & 255;
                    if (d < NOPE) {
                        *(uint32_t*)&g_kh[(((size_t)(b * HH + h)) * SS + sidx) * DQK + d] = pack2(v0, v1);
                    } else {
                        const size_t vb = ((size_t)(b * HH + h)) * VD + (d - NOPE);
                        g_vth[vb * SS + sidx]       = __half_as_ushort(__float2half_rn(v0));
                        g_vth[(vb + 1) * SS + sidx] = __half_as_ushort(__float2half_rn(v1));
                    }
                }
            }
        }
    }
}

// ---------------------------------------------------------------------------
// RoPE, vectorized
// ---------------------------------------------------------------------------
__global__ void rope_kernel(const float* __restrict__ PE,
                            const float* __restrict__ cosb,
                            const float* __restrict__ sinb) {
    int tt = blockIdx.x * blockDim.x + threadIdx.x;
    if (tt >= BB * SS * HH) return;
    const int h = tt & 15;
    const int bs = tt >> 4;
    const int b = bs >> 11, s = bs & 2047;
    const size_t base = (((size_t)(b * HH + h)) * SS + s) * DQK + NOPE;
    const size_t pb = (size_t)bs * ROPE;

#pragma unroll
    for (int cch = 0; cch < 4; cch++) {
        const int i0 = cch * 8;
        uint4 vlo = *(const uint4*)(g_qh + base + i0);
        uint4 vhi = *(const uint4*)(g_qh + base + 32 + i0);
        float4 ca = *(const float4*)(cosb + pb + i0);
        float4 cb = *(const float4*)(cosb + pb + i0 + 4);
        float4 sa = *(const float4*)(sinb + pb + i0);
        float4 sb = *(const float4*)(sinb + pb + i0 + 4);
        float4 pa = *(const float4*)(PE + pb + i0);
        float4 pb4 = *(const float4*)(PE + pb + i0 + 4);
        float4 qa = *(const float4*)(PE + pb + 32 + i0);
        float4 qb = *(const float4*)(PE + pb + 32 + i0 + 4);

        const float cc[8] = {ca.x, ca.y, ca.z, ca.w, cb.x, cb.y, cb.z, cb.w};
        const float ss[8] = {sa.x, sa.y, sa.z, sa.w, sb.x, sb.y, sb.z, sb.w};
        const float p1[8] = {pa.x, pa.y, pa.z, pa.w, pb4.x, pb4.y, pb4.z, pb4.w};
        const float p2[8] = {qa.x, qa.y, qa.z, qa.w, qb.x, qb.y, qb.z, qb.w};
        const uint32_t wl[4] = {vlo.x, vlo.y, vlo.z, vlo.w};
        const uint32_t wh[4] = {vhi.x, vhi.y, vhi.z, vhi.w};

        uint32_t ol[4], oh[4], kl[4], kh[4];
#pragma unroll
        for (int k = 0; k < 4; k++) {
            float2 x1 = __half22float2(*(const __half2*)&wl[k]);
            float2 x2 = __half22float2(*(const __half2*)&wh[k]);
            const int e0 = 2 * k, e1 = 2 * k + 1;
            ol[k] = pack2(x1.x * cc[e0] - x2.x * ss[e0], x1.y * cc[e1] - x2.y * ss[e1]);
            oh[k] = pack2(x2.x * cc[e0] + x1.x * ss[e0], x2.y * cc[e1] + x1.y * ss[e1]);
            kl[k] = pack2(p1[e0] * cc[e0] - p2[e0] * ss[e0], p1[e1] * cc[e1] - p2[e1] * ss[e1]);
            kh[k] = pack2(p2[e0] * cc[e0] + p1[e0] * ss[e0], p2[e1] * cc[e1] + p1[e1] * ss[e1]);
        }
        *(uint4*)(g_qh + base + i0)      = make_uint4(ol[0], ol[1], ol[2], ol[3]);
        *(uint4*)(g_qh + base + 32 + i0) = make_uint4(oh[0], oh[1], oh[2], oh[3]);
        *(uint4*)(g_kh + base + i0)      = make_uint4(kl[0], kl[1], kl[2], kl[3]);
        *(uint4*)(g_kh + base + 32 + i0) = make_uint4(kh[0], kh[1], kh[2], kh[3]);
    }
}

// ---------------------------------------------------------------------------
// Flash attention (causal): BQ=128, BK=64, 256 threads (8 warps x m16),
// single-stage K/V smem, 2 CTAs/SM (occupancy-based load/compute overlap).
// log2-space softmax (exp2f).
// ---------------------------------------------------------------------------
#define QP2 200   // Q/K pitch (halfs)
#define VP2 72    // V pitch (halfs)
#define FK_OFF  (128*QP2)
#define FV_OFF  (FK_OFF + 64*QP2)
#define FL_SMEM_BYTES ((FV_OFF + 128*VP2) * 2)   // 95232 B

extern __shared__ unsigned short fsm2[];

__global__ __launch_bounds__(256, 2) void flash_kernel(float* __restrict__ out) {
    const int qt = gridDim.x - 1 - blockIdx.x;   // heavy CTAs first
    const int h = blockIdx.y, b = blockIdx.z;
    const int tid = threadIdx.x;
    const int w = tid >> 5, lane = tid & 31;
    const int g = lane >> 2, t = lane & 3;
    const int lrow = lane & 15, lc8 = (lane >> 4) << 3;

    const uint32_t uS  = smem_u32(fsm2);
    const uint32_t uQh = uS;
    const uint32_t uKh = uS + FK_OFF * 2;
    const uint32_t uVh = uS + FV_OFF * 2;

    const int wm = w * 16;
    const int q0 = qt * 128;
    const size_t bh = (size_t)(b * HH + h);
    const size_t qgbase = (bh * SS + q0) * DQK;
    const size_t kgbase = bh * SS * DQK;
    const size_t vgbase = bh * VD * SS;

    const int krow[6] = {(tid + 0) / 24, (tid + 256) / 24, (tid + 512) / 24,
                         (tid + 768) / 24, (tid + 1024) / 24, (tid + 1280) / 24};
    const int kseg[6] = {(tid + 0) % 24, (tid + 256) % 24, (tid + 512) % 24,
                         (tid + 768) % 24, (tid + 1024) % 24, (tid + 1280) % 24};
    const int vrow[4] = {(tid + 0) >> 3, (tid + 256) >> 3, (tid + 512) >> 3, (tid + 768) >> 3};
    const int vseg[4] = {(tid + 0) & 7, (tid + 256) & 7, (tid + 512) & 7, (tid + 768) & 7};

    // Q tile load (async, drained by first CP_WAIT(0))
#pragma unroll
    for (int i = 0; i < 12; i++) {
        int idx = tid + i * 256;
        int r = idx / 24, sg = idx % 24;
        cpasync16(uQh + (uint32_t)((r * QP2 + sg * 8) * 2),
                  g_qh + qgbase + (size_t)r * DQK + sg * 8);
    }
    CP_COMMIT();

    const int r0g = q0 + wm + g;
    const int r1g = r0g + 8;

    float po[16][4] = {};
    float m0 = -1e30f, m1 = -1e30f, l0 = 0.f, l1 = 0.f;

    const int nkt = 2 * (qt + 1);
    for (int kt = 0; kt < nkt; kt++) {
        const int k0 = kt << 6;
        // single-stage load of K/V tile kt
#pragma unroll
        for (int i = 0; i < 6; i++)
            cpasync16(uKh + (uint32_t)((krow[i] * QP2 + kseg[i] * 8) * 2),
                      g_kh + kgbase + (size_t)(k0 + krow[i]) * DQK + kseg[i] * 8);
#pragma unroll
        for (int i = 0; i < 4; i++)
            cpasync16(uVh + (uint32_t)((vrow[i] * VP2 + vseg[i] * 8) * 2),
                      g_vth + vgbase + (size_t)vrow[i] * SS + k0 + vseg[i] * 8);
        CP_COMMIT();
        CP_WAIT(0);
        __syncthreads();

        if (k0 <= q0 + wm + 15) {   // warp-tile not fully masked
            // ---- scores ----
            float sc[8][4] = {};
#pragma unroll
            for (int kk = 0; kk < 12; kk++) {
                const int kb = kk << 4;
                uint32_t ah[4];
                ldsm4(ah, uQh + (uint32_t)(((wm + lrow) * QP2 + kb + lc8) * 2));
#pragma unroll
                for (int p = 0; p < 4; p++) {
                    uint32_t b4h[4];
                    ldsm4(b4h, uKh + (uint32_t)(((p * 16 + lrow) * QP2 + kb + lc8) * 2));
                    uint32_t bhe[2] = {b4h[0], b4h[2]}, bho[2] = {b4h[1], b4h[3]};
                    mma16(sc[2 * p],     ah, bhe);
                    mma16(sc[2 * p + 1], ah, bho);
                }
            }

            // ---- mask + scale(log2) + register online softmax ----
            const bool needmask = (k0 + 63 > r0g);
            float mx0 = -1e30f, mx1 = -1e30f;
#pragma unroll
            for (int nf = 0; nf < 8; nf++) {
                const int c0 = k0 + nf * 8 + (t << 1);
                if (needmask) {
                    sc[nf][0] = (c0     > r0g) ? -1e30f : sc[nf][0] * SCALE2;
                    sc[nf][1] = (c0 + 1 > r0g) ? -1e30f : sc[nf][1] * SCALE2;
                    sc[nf][2] = (c0     > r1g) ? -1e30f : sc[nf][2] * SCALE2;
                    sc[nf][3] = (c0 + 1 > r1g) ? -1e30f : sc[nf][3] * SCALE2;
                } else {
                    sc[nf][0] *= SCALE2; sc[nf][1] *= SCALE2;
                    sc[nf][2] *= SCALE2; sc[nf][3] *= SCALE2;
                }
                mx0 = fmaxf(mx0, fmaxf(sc[nf][0], sc[nf][1]));
                mx1 = fmaxf(mx1, fmaxf(sc[nf][2], sc[nf][3]));
            }
            mx0 = fmaxf(mx0, __shfl_xor_sync(0xffffffffu, mx0, 1));
            mx0 = fmaxf(mx0, __shfl_xor_sync(0xffffffffu, mx0, 2));
            mx1 = fmaxf(mx1, __shfl_xor_sync(0xffffffffu, mx1, 1));
            mx1 = fmaxf(mx1, __shfl_xor_sync(0xffffffffu, mx1, 2));
            mx0 = fmaxf(mx0, m0);
            mx1 = fmaxf(mx1, m1);
            const float al0 = exp2f(m0 - mx0);
            const float al1 = exp2f(m1 - mx1);
            m0 = mx0; m1 = mx1;

            uint32_t pah[4][4];
            float s0 = 0.f, s1 = 0.f;
#pragma unroll
            for (int j = 0; j < 4; j++) {
                float p00 = exp2f(sc[2 * j][0] - mx0), p01 = exp2f(sc[2 * j][1] - mx0);
                float p10 = exp2f(sc[2 * j][2] - mx1), p11 = exp2f(sc[2 * j][3] - mx1);
                float q00 = exp2f(sc[2 * j + 1][0] - mx0), q01 = exp2f(sc[2 * j + 1][1] - mx0);
                float q10 = exp2f(sc[2 * j + 1][2] - mx1), q11 = exp2f(sc[2 * j + 1][3] - mx1);
                s0 += p00 + p01 + q00 + q01;
                s1 += p10 + p11 + q10 + q11;
                pah[j][0] = pack2(p00, p01);
                pah[j][1] = pack2(p10, p11);
                pah[j][2] = pack2(q00, q01);
                pah[j][3] = pack2(q10, q11);
            }
            s0 += __shfl_xor_sync(0xffffffffu, s0, 1);
            s0 += __shfl_xor_sync(0xffffffffu, s0, 2);
            s1 += __shfl_xor_sync(0xffffffffu, s1, 1);
            s1 += __shfl_xor_sync(0xffffffffu, s1, 2);
            l0 = l0 * al0 + s0;
            l1 = l1 * al1 + s1;

            // ---- PV ----
#pragma unroll
            for (int nf = 0; nf < 16; nf++) {
                po[nf][0] *= al0; po[nf][1] *= al0;
                po[nf][2] *= al1; po[nf][3] *= al1;
            }
#pragma unroll
            for (int j = 0; j < 4; j++) {
                const int kb = j << 4;
#pragma unroll
                for (int p = 0; p < 8; p++) {
                    uint32_t b4h[4];
                    ldsm4(b4h, uVh + (uint32_t)(((p * 16 + lrow) * VP2 + kb + lc8) * 2));
                    uint32_t bhe[2] = {b4h[0], b4h[2]}, bho[2] = {b4h[1], b4h[3]};
                    mma16(po[2 * p],     pah[j], bhe);
                    mma16(po[2 * p + 1], pah[j], bho);
                }
            }
        }
        __syncthreads();   // protect K/V smem before next tile's overwrite
    }

    // epilogue
    {
        const float iv0 = 1.f / l0;
        const float iv1 = 1.f / l1;
        const size_t ob0 = (((size_t)b * SS + r0g) * HH + h) * VD;
        const size_t ob1 = (((size_t)b * SS + r1g) * HH + h) * VD;
#pragma unroll
        for (int nf = 0; nf < 16; nf++) {
            const int cl = nf * 8 + (t << 1);
            *(float2*)&out[ob0 + cl] = make_float2(po[nf][0] * iv0, po[nf][1] * iv0);
            *(float2*)&out[ob1 + cl] = make_float2(po[nf][2] * iv1, po[nf][3] * iv1);
        }
    }
}

// ---------------------------------------------------------------------------
extern "C" void kernel_launch(void* const* d_in, const int* in_sizes, int n_in,
                              void* d_out, int out_size) {
    const float* Q    = (const float*)d_in[0];
    const float* KV   = (const float*)d_in[1];
    const float* PE   = (const float*)d_in[2];
    const float* WUQ  = (const float*)d_in[3];
    const float* WUKV = (const float*)d_in[4];
    const float* cosb = (const float*)d_in[5];
    const float* sinb = (const float*)d_in[6];
    float* out = (float*)d_out;
    (void)in_sizes; (void)n_in; (void)out_size;

    cudaFuncSetAttribute(flash_kernel, cudaFuncAttributeMaxDynamicSharedMemorySize,
                         FL_SMEM_BYTES);
    cudaFuncSetAttribute(gemm_all_kernel, cudaFuncAttributeMaxDynamicSharedMemorySize,
                         GSMEM_TOTAL);

    presplit_all_kernel<<<(N4_TOT + 255) / 256, 256>>>(Q, KV, WUQ, WUKV);

    gemm_all_kernel<<<G_TOTAL, 512, GSMEM_TOTAL>>>();

    int nrope = BB * SS * HH;
    rope_kernel<<<(nrope + 255) / 256, 256>>>(PE, cosb, sinb);

    dim3 gf(SS / 128, HH, BB);     // (16, 16, 2)
    flash_kernel<<<gf, 256, FL_SMEM_BYTES>>>(out);
}